// round 2
// baseline (speedup 1.0000x reference)
#include <cuda_runtime.h>
#include <cuda_bf16.h>
#include <cstdint>

// Problem constants (fixed shapes from reference setup_inputs)
#define BB 4
#define NN 8192
#define MM 4096
#define FF 64
#define KK 16
#define BM (BB * MM)        // 16384 queries total

// Scan configuration
#define SCAN_THREADS 128
#define S_CHUNKS 4
#define CHUNK (NN / S_CHUNKS)   // 2048
#define CAP 8

#define MIN_SIGMA_C 0.0001f
#define FLTMAX 3.402823466e+38f

// -------- static device scratch (no allocations allowed) --------
__device__ float g_scratchS[S_CHUNKS * 16 * BM];   // candidate scores, layout [(c*16+j)][q]
__device__ int   g_scratchI[S_CHUNKS * 16 * BM];   // candidate indices
__device__ float g_featT[(size_t)BB * NN * FF];    // transposed features (B, N, F)

// -------- sorted-16 insertion (ascending, s[15] = worst) --------
__device__ __forceinline__ void insert16(float v, int n, float s[16], int si[16]) {
    if (v < s[15]) {
        s[15] = v; si[15] = n;
#pragma unroll
        for (int i = 15; i > 0; --i) {
            if (s[i] < s[i - 1]) {
                float tv = s[i]; s[i] = s[i - 1]; s[i - 1] = tv;
                int ti = si[i]; si[i] = si[i - 1]; si[i - 1] = ti;
            }
        }
    }
}

// ================= Kernel 1: feature transpose (B,F,N) -> (B,N,F) =================
__global__ void transpose_kernel(const float* __restrict__ feat) {
    __shared__ float tile[32][33];
    int b  = blockIdx.z;
    int f0 = blockIdx.y * 32;
    int n0 = blockIdx.x * 32;
    int tx = threadIdx.x, ty = threadIdx.y;   // block (32, 8)
#pragma unroll
    for (int i = ty; i < 32; i += 8)
        tile[i][tx] = feat[((size_t)b * FF + (f0 + i)) * NN + n0 + tx];
    __syncthreads();
#pragma unroll
    for (int i = ty; i < 32; i += 8)
        g_featT[((size_t)b * NN + (n0 + i)) * FF + f0 + tx] = tile[tx][i];
}

// ================= Kernel 2: per-chunk top-16 scan =================
// grid: (MM/SCAN_THREADS, BB, S_CHUNKS), block: SCAN_THREADS
// Each thread owns one query; all threads in the block share one N-chunk in smem.
// score = |p|^2 - 2 q.p  (monotonic in d2 for fixed q -> valid for selection)
__global__ __launch_bounds__(SCAN_THREADS, 4)
void scan_kernel(const float* __restrict__ pc, const float* __restrict__ qc) {
    __shared__ float4 spts[CHUNK];                 // (x, y, z, |p|^2)  32 KB
    __shared__ float  bufS[CAP][SCAN_THREADS];     // 4 KB, conflict-free [slot][tid]
    __shared__ int    bufI[CAP][SCAN_THREADS];     // 4 KB

    const int tid = threadIdx.x;
    const int mt  = blockIdx.x;
    const int b   = blockIdx.y;
    const int c   = blockIdx.z;
    const int m   = mt * SCAN_THREADS + tid;
    const int n0  = c * CHUNK;

    const float* pcb = pc + (size_t)b * 3 * NN;
    for (int t = tid; t < CHUNK; t += SCAN_THREADS) {
        float x = pcb[n0 + t];
        float y = pcb[NN + n0 + t];
        float z = pcb[2 * NN + n0 + t];
        spts[t] = make_float4(x, y, z, fmaf(x, x, fmaf(y, y, z * z)));
    }
    __syncthreads();

    const float* qcb = qc + (size_t)b * 3 * MM;
    const float qx2 = -2.0f * qcb[m];
    const float qy2 = -2.0f * qcb[MM + m];
    const float qz2 = -2.0f * qcb[2 * MM + m];

    float s[16]; int si[16];
#pragma unroll
    for (int i = 0; i < 16; ++i) { s[i] = FLTMAX; si[i] = -1; }
    int cnt = 0;

#pragma unroll 4
    for (int t = 0; t < CHUNK; ++t) {
        float4 p = spts[t];
        float sc = fmaf(p.x, qx2, fmaf(p.y, qy2, fmaf(p.z, qz2, p.w)));
        if (sc < s[15]) {                       // cheap predicated append
            bufS[cnt][tid] = sc;
            bufI[cnt][tid] = n0 + t;
            ++cnt;
            if (cnt == CAP) {                   // rare: merge buffer into sorted list
#pragma unroll
                for (int j = 0; j < CAP; ++j)
                    insert16(bufS[j][tid], bufI[j][tid], s, si);
                cnt = 0;
            }
        }
    }
    for (int j = 0; j < cnt; ++j)               // final partial flush
        insert16(bufS[j][tid], bufI[j][tid], s, si);

    const int q = b * MM + m;
#pragma unroll
    for (int j = 0; j < 16; ++j) {              // coalesced across q
        g_scratchS[(c * 16 + j) * BM + q] = s[j];
        g_scratchI[(c * 16 + j) * BM + q] = si[j];
    }
}

// ================= Kernel 3: merge candidates, softmax, outputs =================
// grid: BM/128, block: 128. One thread per query.
__global__ __launch_bounds__(128)
void merge_kernel(const float* __restrict__ pc, const float* __restrict__ qc,
                  const float* __restrict__ temp, float* __restrict__ out) {
    const int q = blockIdx.x * blockDim.x + threadIdx.x;
    const int b = q / MM;
    const int m = q - b * MM;

    // ---- merge 4 sorted chunk lists (64 candidates) into final top-16 ----
    float s[16]; int si[16];
#pragma unroll
    for (int i = 0; i < 16; ++i) { s[i] = FLTMAX; si[i] = -1; }
#pragma unroll
    for (int c = 0; c < S_CHUNKS; ++c)
#pragma unroll
        for (int j = 0; j < 16; ++j)
            insert16(g_scratchS[(c * 16 + j) * BM + q],
                     g_scratchI[(c * 16 + j) * BM + q], s, si);

    const float* pcb = pc + (size_t)b * 3 * NN;
    const float* qcb = qc + (size_t)b * 3 * MM;
    const float qx = qcb[m], qy = qcb[MM + m], qz = qcb[2 * MM + m];

    // ---- exact d2 (matches reference weight formula), find min ----
    float d2[16];
    float mind = FLTMAX;
#pragma unroll
    for (int j = 0; j < 16; ++j) {
        int n = si[j];
        float dx = pcb[n] - qx;
        float dy = pcb[NN + n] - qy;
        float dz = pcb[2 * NN + n] - qz;
        d2[j] = fmaf(dx, dx, fmaf(dy, dy, dz * dz));
        mind = fminf(mind, d2[j]);
    }

    float tv = temp[0];
    float sigma = fmaxf(tv * tv, MIN_SIGMA_C);
    float inv_sigma = 1.0f / sigma;

    float w[16];
    float wsum = 0.0f;
#pragma unroll
    for (int j = 0; j < 16; ++j) {
        w[j] = __expf((mind - d2[j]) * inv_sigma);
        wsum += w[j];
    }
    float r = 1.0f / wsum;
#pragma unroll
    for (int j = 0; j < 16; ++j) w[j] *= r;

    // ---- projected points (reload coords: L1/L2 hot) ----
    float ox = 0.f, oy = 0.f, oz = 0.f;
#pragma unroll
    for (int j = 0; j < 16; ++j) {
        int n = si[j];
        ox = fmaf(w[j], pcb[n], ox);
        oy = fmaf(w[j], pcb[NN + n], oy);
        oz = fmaf(w[j], pcb[2 * NN + n], oz);
    }
    out[(b * 3 + 0) * MM + m] = ox;   // coalesced across m
    out[(b * 3 + 1) * MM + m] = oy;
    out[(b * 3 + 2) * MM + m] = oz;

    // ---- feature accumulation from transposed features (contiguous 256B/neighbor) ----
    float* outf = out + (size_t)BB * 3 * MM;
#pragma unroll
    for (int fc = 0; fc < FF / 16; ++fc) {       // 16 features per pass (4 float4 accumulators)
        float4 a0 = make_float4(0.f, 0.f, 0.f, 0.f);
        float4 a1 = a0, a2 = a0, a3 = a0;
#pragma unroll
        for (int j = 0; j < 16; ++j) {
            const float4* fp = reinterpret_cast<const float4*>(
                &g_featT[((size_t)b * NN + si[j]) * FF + fc * 16]);
            float wj = w[j];
            float4 v0 = fp[0], v1 = fp[1], v2 = fp[2], v3 = fp[3];
            a0.x = fmaf(wj, v0.x, a0.x); a0.y = fmaf(wj, v0.y, a0.y);
            a0.z = fmaf(wj, v0.z, a0.z); a0.w = fmaf(wj, v0.w, a0.w);
            a1.x = fmaf(wj, v1.x, a1.x); a1.y = fmaf(wj, v1.y, a1.y);
            a1.z = fmaf(wj, v1.z, a1.z); a1.w = fmaf(wj, v1.w, a1.w);
            a2.x = fmaf(wj, v2.x, a2.x); a2.y = fmaf(wj, v2.y, a2.y);
            a2.z = fmaf(wj, v2.z, a2.z); a2.w = fmaf(wj, v2.w, a2.w);
            a3.x = fmaf(wj, v3.x, a3.x); a3.y = fmaf(wj, v3.y, a3.y);
            a3.z = fmaf(wj, v3.z, a3.z); a3.w = fmaf(wj, v3.w, a3.w);
        }
        int f0 = fc * 16;
        // coalesced across m for each scalar f
        outf[((size_t)b * FF + f0 +  0) * MM + m] = a0.x;
        outf[((size_t)b * FF + f0 +  1) * MM + m] = a0.y;
        outf[((size_t)b * FF + f0 +  2) * MM + m] = a0.z;
        outf[((size_t)b * FF + f0 +  3) * MM + m] = a0.w;
        outf[((size_t)b * FF + f0 +  4) * MM + m] = a1.x;
        outf[((size_t)b * FF + f0 +  5) * MM + m] = a1.y;
        outf[((size_t)b * FF + f0 +  6) * MM + m] = a1.z;
        outf[((size_t)b * FF + f0 +  7) * MM + m] = a1.w;
        outf[((size_t)b * FF + f0 +  8) * MM + m] = a2.x;
        outf[((size_t)b * FF + f0 +  9) * MM + m] = a2.y;
        outf[((size_t)b * FF + f0 + 10) * MM + m] = a2.z;
        outf[((size_t)b * FF + f0 + 11) * MM + m] = a2.w;
        outf[((size_t)b * FF + f0 + 12) * MM + m] = a3.x;
        outf[((size_t)b * FF + f0 + 13) * MM + m] = a3.y;
        outf[((size_t)b * FF + f0 + 14) * MM + m] = a3.z;
        outf[((size_t)b * FF + f0 + 15) * MM + m] = a3.w;
    }
}

// ================= launch =================
extern "C" void kernel_launch(void* const* d_in, const int* in_sizes, int n_in,
                              void* d_out, int out_size) {
    const float* point_cloud    = (const float*)d_in[0];  // (B, 3, N)
    const float* query_cloud    = (const float*)d_in[1];  // (B, 3, M)
    const float* point_features = (const float*)d_in[2];  // (B, F, N)
    const float* temperature    = (const float*)d_in[3];  // scalar
    float* out = (float*)d_out;  // [projected (B,3,M) | propagated (B,F,M)]

    (void)in_sizes; (void)n_in; (void)out_size;

    dim3 tgrid(NN / 32, FF / 32, BB);
    dim3 tblk(32, 8);
    transpose_kernel<<<tgrid, tblk>>>(point_features);

    dim3 sgrid(MM / SCAN_THREADS, BB, S_CHUNKS);
    scan_kernel<<<sgrid, SCAN_THREADS>>>(point_cloud, query_cloud);

    merge_kernel<<<BM / 128, 128>>>(point_cloud, query_cloud, temperature, out);
}

// round 3
// speedup vs baseline: 6.3060x; 6.3060x over previous
#include <cuda_runtime.h>
#include <cuda_bf16.h>
#include <cstdint>

// Problem constants (fixed shapes from reference setup_inputs)
#define BB 4
#define NN 8192
#define MM 4096
#define FF 64
#define KK 16
#define BM (BB * MM)        // 16384 queries total

// Scan configuration
#define SCAN_THREADS 128
#define S_CHUNKS 4
#define CHUNK (NN / S_CHUNKS)   // 2048

#define MIN_SIGMA_C 0.0001f
#define FLTMAX 3.402823466e+38f

// -------- static device scratch (no allocations allowed) --------
__device__ float g_scratchS[S_CHUNKS * 16 * BM];   // candidate scores, layout [(c*16+j)][q]
__device__ int   g_scratchI[S_CHUNKS * 16 * BM];   // candidate indices
__device__ float g_featT[(size_t)BB * NN * FF];    // transposed features (B, N, F)

// -------- branchless conditional-shift insert into sorted-ascending 16 list --------
// Caller guarantees v < s[15]. Dependency depth ~3 (parallel FSETPs, FMNMX pair, selects).
__device__ __forceinline__ void insert_shift(float v, int vi, float s[16], int si[16]) {
    bool c[16];
#pragma unroll
    for (int i = 0; i < 16; ++i) c[i] = v < s[i];     // 16 independent compares
#pragma unroll
    for (int i = 15; i >= 1; --i) {
        // scores: min(max(v, s[i-1]), s[i]) == shift-insert (2 FMNMX, no predicate)
        s[i]  = fminf(fmaxf(v, s[i - 1]), s[i]);
        // indices: c[i-1] -> take s[i-1]'s idx; else if c[i] -> v's idx; else keep
        si[i] = c[i - 1] ? si[i - 1] : (c[i] ? vi : si[i]);
    }
    si[0] = c[0] ? vi : si[0];
    s[0]  = fminf(v, s[0]);
}

// ================= Kernel 1: feature transpose (B,F,N) -> (B,N,F) =================
__global__ void transpose_kernel(const float* __restrict__ feat) {
    __shared__ float tile[32][33];
    int b  = blockIdx.z;
    int f0 = blockIdx.y * 32;
    int n0 = blockIdx.x * 32;
    int tx = threadIdx.x, ty = threadIdx.y;   // block (32, 8)
#pragma unroll
    for (int i = ty; i < 32; i += 8)
        tile[i][tx] = feat[((size_t)b * FF + (f0 + i)) * NN + n0 + tx];
    __syncthreads();
#pragma unroll
    for (int i = ty; i < 32; i += 8)
        g_featT[((size_t)b * NN + (n0 + i)) * FF + f0 + tx] = tile[tx][i];
}

// ================= Kernel 2: per-chunk top-16 scan =================
// grid: (MM/SCAN_THREADS, BB, S_CHUNKS), block: SCAN_THREADS
// Each thread owns one query; block shares one N-chunk in smem.
// score = |p|^2 - 2 q.p  (monotone in d2 for fixed q -> valid for selection)
__global__ __launch_bounds__(SCAN_THREADS, 4)
void scan_kernel(const float* __restrict__ pc, const float* __restrict__ qc) {
    __shared__ float4 spts[CHUNK];                 // (x, y, z, |p|^2)  32 KB

    const int tid = threadIdx.x;
    const int m   = blockIdx.x * SCAN_THREADS + tid;
    const int b   = blockIdx.y;
    const int c   = blockIdx.z;
    const int n0  = c * CHUNK;

    const float* pcb = pc + (size_t)b * 3 * NN;
    for (int t = tid; t < CHUNK; t += SCAN_THREADS) {
        float x = pcb[n0 + t];
        float y = pcb[NN + n0 + t];
        float z = pcb[2 * NN + n0 + t];
        spts[t] = make_float4(x, y, z, fmaf(x, x, fmaf(y, y, z * z)));
    }
    __syncthreads();

    const float* qcb = qc + (size_t)b * 3 * MM;
    const float qx2 = -2.0f * qcb[m];
    const float qy2 = -2.0f * qcb[MM + m];
    const float qz2 = -2.0f * qcb[2 * MM + m];

    float s[16]; int si[16];
#pragma unroll
    for (int i = 0; i < 16; ++i) { s[i] = FLTMAX; si[i] = -1; }
    float thr = FLTMAX;

#pragma unroll 4
    for (int t = 0; t < CHUNK; ++t) {
        float4 p = spts[t];
        float sc = fmaf(p.x, qx2, fmaf(p.y, qy2, fmaf(p.z, qz2, p.w)));
        if (sc < thr) {                        // rare; register-only body
            insert_shift(sc, n0 + t, s, si);
            thr = s[15];
        }
    }

    const int q = b * MM + m;
#pragma unroll
    for (int j = 0; j < 16; ++j) {              // coalesced across q
        g_scratchS[(c * 16 + j) * BM + q] = s[j];
        g_scratchI[(c * 16 + j) * BM + q] = si[j];
    }
}

// ================= Kernel 3: merge candidates, softmax, outputs =================
// grid: BM/128, block: 128. One thread per query.
__global__ __launch_bounds__(128)
void merge_kernel(const float* __restrict__ pc, const float* __restrict__ qc,
                  const float* __restrict__ temp, float* __restrict__ out) {
    const int q = blockIdx.x * blockDim.x + threadIdx.x;
    const int b = q / MM;
    const int m = q - b * MM;

    // ---- merge 4 sorted chunk lists (64 candidates) into final top-16 ----
    float s[16]; int si[16];
#pragma unroll
    for (int i = 0; i < 16; ++i) { s[i] = FLTMAX; si[i] = -1; }
#pragma unroll
    for (int c = 0; c < S_CHUNKS; ++c)
#pragma unroll
        for (int j = 0; j < 16; ++j) {
            float v = g_scratchS[(c * 16 + j) * BM + q];
            int  vi = g_scratchI[(c * 16 + j) * BM + q];
            if (v < s[15]) insert_shift(v, vi, s, si);
        }

    const float* pcb = pc + (size_t)b * 3 * NN;
    const float* qcb = qc + (size_t)b * 3 * MM;
    const float qx = qcb[m], qy = qcb[MM + m], qz = qcb[2 * MM + m];

    // ---- exact d2 (matches reference weight formula), find min ----
    float d2[16];
    float mind = FLTMAX;
#pragma unroll
    for (int j = 0; j < 16; ++j) {
        int n = si[j];
        float dx = pcb[n] - qx;
        float dy = pcb[NN + n] - qy;
        float dz = pcb[2 * NN + n] - qz;
        d2[j] = fmaf(dx, dx, fmaf(dy, dy, dz * dz));
        mind = fminf(mind, d2[j]);
    }

    float tv = temp[0];
    float sigma = fmaxf(tv * tv, MIN_SIGMA_C);
    float inv_sigma = 1.0f / sigma;

    float w[16];
    float wsum = 0.0f;
#pragma unroll
    for (int j = 0; j < 16; ++j) {
        w[j] = __expf((mind - d2[j]) * inv_sigma);
        wsum += w[j];
    }
    float r = 1.0f / wsum;
#pragma unroll
    for (int j = 0; j < 16; ++j) w[j] *= r;

    // ---- projected points (reload coords: L1/L2 hot) ----
    float ox = 0.f, oy = 0.f, oz = 0.f;
#pragma unroll
    for (int j = 0; j < 16; ++j) {
        int n = si[j];
        ox = fmaf(w[j], pcb[n], ox);
        oy = fmaf(w[j], pcb[NN + n], oy);
        oz = fmaf(w[j], pcb[2 * NN + n], oz);
    }
    out[(b * 3 + 0) * MM + m] = ox;   // coalesced across m
    out[(b * 3 + 1) * MM + m] = oy;
    out[(b * 3 + 2) * MM + m] = oz;

    // ---- feature accumulation from transposed features (contiguous 256B/neighbor) ----
    float* outf = out + (size_t)BB * 3 * MM;
#pragma unroll
    for (int fc = 0; fc < FF / 16; ++fc) {       // 16 features per pass
        float4 a0 = make_float4(0.f, 0.f, 0.f, 0.f);
        float4 a1 = a0, a2 = a0, a3 = a0;
#pragma unroll
        for (int j = 0; j < 16; ++j) {
            const float4* fp = reinterpret_cast<const float4*>(
                &g_featT[((size_t)b * NN + si[j]) * FF + fc * 16]);
            float wj = w[j];
            float4 v0 = fp[0], v1 = fp[1], v2 = fp[2], v3 = fp[3];
            a0.x = fmaf(wj, v0.x, a0.x); a0.y = fmaf(wj, v0.y, a0.y);
            a0.z = fmaf(wj, v0.z, a0.z); a0.w = fmaf(wj, v0.w, a0.w);
            a1.x = fmaf(wj, v1.x, a1.x); a1.y = fmaf(wj, v1.y, a1.y);
            a1.z = fmaf(wj, v1.z, a1.z); a1.w = fmaf(wj, v1.w, a1.w);
            a2.x = fmaf(wj, v2.x, a2.x); a2.y = fmaf(wj, v2.y, a2.y);
            a2.z = fmaf(wj, v2.z, a2.z); a2.w = fmaf(wj, v2.w, a2.w);
            a3.x = fmaf(wj, v3.x, a3.x); a3.y = fmaf(wj, v3.y, a3.y);
            a3.z = fmaf(wj, v3.z, a3.z); a3.w = fmaf(wj, v3.w, a3.w);
        }
        int f0 = fc * 16;
        outf[((size_t)b * FF + f0 +  0) * MM + m] = a0.x;
        outf[((size_t)b * FF + f0 +  1) * MM + m] = a0.y;
        outf[((size_t)b * FF + f0 +  2) * MM + m] = a0.z;
        outf[((size_t)b * FF + f0 +  3) * MM + m] = a0.w;
        outf[((size_t)b * FF + f0 +  4) * MM + m] = a1.x;
        outf[((size_t)b * FF + f0 +  5) * MM + m] = a1.y;
        outf[((size_t)b * FF + f0 +  6) * MM + m] = a1.z;
        outf[((size_t)b * FF + f0 +  7) * MM + m] = a1.w;
        outf[((size_t)b * FF + f0 +  8) * MM + m] = a2.x;
        outf[((size_t)b * FF + f0 +  9) * MM + m] = a2.y;
        outf[((size_t)b * FF + f0 + 10) * MM + m] = a2.z;
        outf[((size_t)b * FF + f0 + 11) * MM + m] = a2.w;
        outf[((size_t)b * FF + f0 + 12) * MM + m] = a3.x;
        outf[((size_t)b * FF + f0 + 13) * MM + m] = a3.y;
        outf[((size_t)b * FF + f0 + 14) * MM + m] = a3.z;
        outf[((size_t)b * FF + f0 + 15) * MM + m] = a3.w;
    }
}

// ================= launch =================
extern "C" void kernel_launch(void* const* d_in, const int* in_sizes, int n_in,
                              void* d_out, int out_size) {
    const float* point_cloud    = (const float*)d_in[0];  // (B, 3, N)
    const float* query_cloud    = (const float*)d_in[1];  // (B, 3, M)
    const float* point_features = (const float*)d_in[2];  // (B, F, N)
    const float* temperature    = (const float*)d_in[3];  // scalar
    float* out = (float*)d_out;  // [projected (B,3,M) | propagated (B,F,M)]

    (void)in_sizes; (void)n_in; (void)out_size;

    dim3 tgrid(NN / 32, FF / 32, BB);
    dim3 tblk(32, 8);
    transpose_kernel<<<tgrid, tblk>>>(point_features);

    dim3 sgrid(MM / SCAN_THREADS, BB, S_CHUNKS);
    scan_kernel<<<sgrid, SCAN_THREADS>>>(point_cloud, query_cloud);

    merge_kernel<<<BM / 128, 128>>>(point_cloud, query_cloud, temperature, out);
}

// round 4
// speedup vs baseline: 19.6806x; 3.1209x over previous
#include <cuda_runtime.h>
#include <cuda_bf16.h>
#include <cstdint>

// Problem constants (fixed shapes from reference setup_inputs)
#define BB 4
#define NN 8192
#define MM 4096
#define FF 64
#define KK 16
#define BM (BB * MM)        // 16384 queries total

// Scan configuration: one warp per query, 16 queries per block
#define QW 16
#define SCAN_TPB (QW * 32)      // 512
#define TILE 2048               // points per smem tile (32 KB of float4)

#define MIN_SIGMA_C 0.0001f
#define FLTMAX 3.402823466e+38f

// -------- static device scratch (no allocations allowed) --------
__device__ int   g_idx[BM * KK];                  // final top-16 indices per query
__device__ float g_featT[(size_t)BB * NN * FF];   // transposed features (B, N, F)

// ================= Kernel 1: feature transpose (B,F,N) -> (B,N,F) =================
__global__ void transpose_kernel(const float* __restrict__ feat) {
    __shared__ float tile[32][33];
    int b  = blockIdx.z;
    int f0 = blockIdx.y * 32;
    int n0 = blockIdx.x * 32;
    int tx = threadIdx.x, ty = threadIdx.y;   // block (32, 8)
#pragma unroll
    for (int i = ty; i < 32; i += 8)
        tile[i][tx] = feat[((size_t)b * FF + (f0 + i)) * NN + n0 + tx];
    __syncthreads();
#pragma unroll
    for (int i = ty; i < 32; i += 8)
        g_featT[((size_t)b * NN + (n0 + i)) * FF + f0 + tx] = tile[tx][i];
}

// ================= Kernel 2: warp-per-query exact top-16 over all N =================
// grid: (MM/QW, BB), block: 512. Warp w owns query m = blockIdx.x*QW + w.
// Sorted ascending list distributed across lanes 0..15 (lane l = slot l).
// score = |p|^2 - 2 q.p  (monotone in d2 for fixed q -> valid for selection)
__global__ __launch_bounds__(SCAN_TPB)
void scan_kernel(const float* __restrict__ pc, const float* __restrict__ qc) {
    __shared__ float4 spts[TILE];                 // (x, y, z, |p|^2)  32 KB

    const int tid  = threadIdx.x;
    const int lane = tid & 31;
    const int w    = tid >> 5;
    const int b    = blockIdx.y;
    const int m    = blockIdx.x * QW + w;

    const float* pcb = pc + (size_t)b * 3 * NN;
    const float* qcb = qc + (size_t)b * 3 * MM;
    const float qx2 = -2.0f * qcb[m];
    const float qy2 = -2.0f * qcb[MM + m];
    const float qz2 = -2.0f * qcb[2 * MM + m];

    float vs  = FLTMAX;     // this lane's slot value (lanes 0..15 meaningful)
    int   vix = 0;          // this lane's slot index
    float thr = FLTMAX;     // = slot 15 value (warp-uniform)

    for (int tile = 0; tile < NN / TILE; ++tile) {
        const int n0 = tile * TILE;
        __syncthreads();
        for (int t = tid; t < TILE; t += SCAN_TPB) {
            float x = pcb[n0 + t];
            float y = pcb[NN + n0 + t];
            float z = pcb[2 * NN + n0 + t];
            spts[t] = make_float4(x, y, z, fmaf(x, x, fmaf(y, y, z * z)));
        }
        __syncthreads();

#pragma unroll 4
        for (int i = 0; i < TILE / 32; ++i) {
            float4 p = spts[i * 32 + lane];
            float sc = fmaf(p.x, qx2, fmaf(p.y, qy2, fmaf(p.z, qz2, p.w)));
            unsigned ball = __ballot_sync(0xffffffffu, sc < thr);
            while (ball) {                         // process candidates in index order
                int src = __ffs(ball) - 1;
                ball &= ball - 1;
                float v = __shfl_sync(0xffffffffu, sc, src);
                if (v < thr) {                     // re-check against tightened thr (uniform)
                    int vi = n0 + i * 32 + src;
                    float prev = __shfl_up_sync(0xffffffffu, vs, 1);
                    int  previ = __shfl_up_sync(0xffffffffu, vix, 1);
                    if (lane == 0) prev = -FLTMAX;
                    bool cprev = v < prev;         // insertion below slot l-1 -> shift
                    bool cm    = v < vs;           // insertion at/above this slot
                    vix = cprev ? previ : (cm ? vi : vix);
                    vs  = fminf(fmaxf(v, prev), vs);
                    thr = __shfl_sync(0xffffffffu, vs, 15);
                }
            }
        }
    }

    if (lane < KK)
        g_idx[(b * MM + m) * KK + lane] = vix;     // sorted ascending by score
}

// ================= Kernel 3: softmax + outputs (one thread per query) =================
__global__ __launch_bounds__(128)
void epilogue_kernel(const float* __restrict__ pc, const float* __restrict__ qc,
                     const float* __restrict__ temp, float* __restrict__ out) {
    const int q = blockIdx.x * blockDim.x + threadIdx.x;
    const int b = q / MM;
    const int m = q - b * MM;

    int si[16];
#pragma unroll
    for (int j = 0; j < 16; ++j) si[j] = g_idx[q * KK + j];

    const float* pcb = pc + (size_t)b * 3 * NN;
    const float* qcb = qc + (size_t)b * 3 * MM;
    const float qx = qcb[m], qy = qcb[MM + m], qz = qcb[2 * MM + m];

    // ---- exact d2 (matches reference weight formula), find min ----
    float d2[16];
    float mind = FLTMAX;
#pragma unroll
    for (int j = 0; j < 16; ++j) {
        int n = si[j];
        float dx = pcb[n] - qx;
        float dy = pcb[NN + n] - qy;
        float dz = pcb[2 * NN + n] - qz;
        d2[j] = fmaf(dx, dx, fmaf(dy, dy, dz * dz));
        mind = fminf(mind, d2[j]);
    }

    float tv = temp[0];
    float sigma = fmaxf(tv * tv, MIN_SIGMA_C);
    float inv_sigma = 1.0f / sigma;

    float w[16];
    float wsum = 0.0f;
#pragma unroll
    for (int j = 0; j < 16; ++j) {
        w[j] = __expf((mind - d2[j]) * inv_sigma);
        wsum += w[j];
    }
    float r = 1.0f / wsum;
#pragma unroll
    for (int j = 0; j < 16; ++j) w[j] *= r;

    // ---- projected points (coords L1/L2 hot) ----
    float ox = 0.f, oy = 0.f, oz = 0.f;
#pragma unroll
    for (int j = 0; j < 16; ++j) {
        int n = si[j];
        ox = fmaf(w[j], pcb[n], ox);
        oy = fmaf(w[j], pcb[NN + n], oy);
        oz = fmaf(w[j], pcb[2 * NN + n], oz);
    }
    out[(b * 3 + 0) * MM + m] = ox;   // coalesced across m
    out[(b * 3 + 1) * MM + m] = oy;
    out[(b * 3 + 2) * MM + m] = oz;

    // ---- feature accumulation from transposed features (contiguous 256B/neighbor) ----
    float* outf = out + (size_t)BB * 3 * MM;
#pragma unroll
    for (int fc = 0; fc < FF / 16; ++fc) {       // 16 features per pass
        float4 a0 = make_float4(0.f, 0.f, 0.f, 0.f);
        float4 a1 = a0, a2 = a0, a3 = a0;
#pragma unroll
        for (int j = 0; j < 16; ++j) {
            const float4* fp = reinterpret_cast<const float4*>(
                &g_featT[((size_t)b * NN + si[j]) * FF + fc * 16]);
            float wj = w[j];
            float4 v0 = fp[0], v1 = fp[1], v2 = fp[2], v3 = fp[3];
            a0.x = fmaf(wj, v0.x, a0.x); a0.y = fmaf(wj, v0.y, a0.y);
            a0.z = fmaf(wj, v0.z, a0.z); a0.w = fmaf(wj, v0.w, a0.w);
            a1.x = fmaf(wj, v1.x, a1.x); a1.y = fmaf(wj, v1.y, a1.y);
            a1.z = fmaf(wj, v1.z, a1.z); a1.w = fmaf(wj, v1.w, a1.w);
            a2.x = fmaf(wj, v2.x, a2.x); a2.y = fmaf(wj, v2.y, a2.y);
            a2.z = fmaf(wj, v2.z, a2.z); a2.w = fmaf(wj, v2.w, a2.w);
            a3.x = fmaf(wj, v3.x, a3.x); a3.y = fmaf(wj, v3.y, a3.y);
            a3.z = fmaf(wj, v3.z, a3.z); a3.w = fmaf(wj, v3.w, a3.w);
        }
        int f0 = fc * 16;
        outf[((size_t)b * FF + f0 +  0) * MM + m] = a0.x;
        outf[((size_t)b * FF + f0 +  1) * MM + m] = a0.y;
        outf[((size_t)b * FF + f0 +  2) * MM + m] = a0.z;
        outf[((size_t)b * FF + f0 +  3) * MM + m] = a0.w;
        outf[((size_t)b * FF + f0 +  4) * MM + m] = a1.x;
        outf[((size_t)b * FF + f0 +  5) * MM + m] = a1.y;
        outf[((size_t)b * FF + f0 +  6) * MM + m] = a1.z;
        outf[((size_t)b * FF + f0 +  7) * MM + m] = a1.w;
        outf[((size_t)b * FF + f0 +  8) * MM + m] = a2.x;
        outf[((size_t)b * FF + f0 +  9) * MM + m] = a2.y;
        outf[((size_t)b * FF + f0 + 10) * MM + m] = a2.z;
        outf[((size_t)b * FF + f0 + 11) * MM + m] = a2.w;
        outf[((size_t)b * FF + f0 + 12) * MM + m] = a3.x;
        outf[((size_t)b * FF + f0 + 13) * MM + m] = a3.y;
        outf[((size_t)b * FF + f0 + 14) * MM + m] = a3.z;
        outf[((size_t)b * FF + f0 + 15) * MM + m] = a3.w;
    }
}

// ================= launch =================
extern "C" void kernel_launch(void* const* d_in, const int* in_sizes, int n_in,
                              void* d_out, int out_size) {
    const float* point_cloud    = (const float*)d_in[0];  // (B, 3, N)
    const float* query_cloud    = (const float*)d_in[1];  // (B, 3, M)
    const float* point_features = (const float*)d_in[2];  // (B, F, N)
    const float* temperature    = (const float*)d_in[3];  // scalar
    float* out = (float*)d_out;  // [projected (B,3,M) | propagated (B,F,M)]

    (void)in_sizes; (void)n_in; (void)out_size;

    dim3 tgrid(NN / 32, FF / 32, BB);
    dim3 tblk(32, 8);
    transpose_kernel<<<tgrid, tblk>>>(point_features);

    dim3 sgrid(MM / QW, BB);
    scan_kernel<<<sgrid, SCAN_TPB>>>(point_cloud, query_cloud);

    epilogue_kernel<<<BM / 128, 128>>>(point_cloud, query_cloud, temperature, out);
}

// round 5
// speedup vs baseline: 20.6894x; 1.0513x over previous
#include <cuda_runtime.h>
#include <cuda_bf16.h>
#include <cstdint>

// Problem constants (fixed shapes from reference setup_inputs)
#define BB 4
#define NN 8192
#define MM 4096
#define FF 64
#define KK 16
#define BM (BB * MM)        // 16384 queries total

// Scan configuration: one warp per query, 16 queries per block
#define QW 16
#define SCAN_TPB (QW * 32)      // 512
#define TILE 2048               // points per smem tile (32 KB of float4)

#define MIN_SIGMA_C 0.0001f
#define FLTMAX 3.402823466e+38f

// -------- static device scratch (no allocations allowed) --------
__device__ float g_featT[(size_t)BB * NN * FF];   // transposed features (B, N, F)

// ================= Kernel 1: feature transpose (B,F,N) -> (B,N,F) =================
__global__ void transpose_kernel(const float* __restrict__ feat) {
    __shared__ float tile[32][33];
    int b  = blockIdx.z;
    int f0 = blockIdx.y * 32;
    int n0 = blockIdx.x * 32;
    int tx = threadIdx.x, ty = threadIdx.y;   // block (32, 8)
#pragma unroll
    for (int i = ty; i < 32; i += 8)
        tile[i][tx] = feat[((size_t)b * FF + (f0 + i)) * NN + n0 + tx];
    __syncthreads();
#pragma unroll
    for (int i = ty; i < 32; i += 8)
        g_featT[((size_t)b * NN + (n0 + i)) * FF + f0 + tx] = tile[tx][i];
}

// ================= Kernel 2: fused warp-per-query top-16 + softmax + outputs ======
// grid: (MM/QW, BB), block: 512. Warp w owns query m = blockIdx.x*QW + w.
// Sorted ascending list distributed across lanes 0..15 (lane l = slot l).
// score = |p|^2 - 2 q.p  (monotone in d2 for fixed q -> valid for selection)
__global__ __launch_bounds__(SCAN_TPB)
void fused_kernel(const float* __restrict__ pc, const float* __restrict__ qc,
                  const float* __restrict__ temp, float* __restrict__ out) {
    __shared__ float4 spts[TILE];                 // 32 KB point tile
    __shared__ float  sfeat[QW][FF + 1];          // staged features (pad: conflict-free read)
    __shared__ float  spp[QW][4];                 // staged projected points

    const int tid  = threadIdx.x;
    const int lane = tid & 31;
    const int w    = tid >> 5;
    const int b    = blockIdx.y;
    const int m0   = blockIdx.x * QW;
    const int m    = m0 + w;

    const float* pcb = pc + (size_t)b * 3 * NN;
    const float* qcb = qc + (size_t)b * 3 * MM;
    const float qx = qcb[m];
    const float qy = qcb[MM + m];
    const float qz = qcb[2 * MM + m];
    const float qx2 = -2.0f * qx, qy2 = -2.0f * qy, qz2 = -2.0f * qz;

    float vs  = FLTMAX;     // this lane's slot value (lanes 0..15 meaningful)
    int   vix = 0;          // this lane's slot index
    float thr = FLTMAX;     // = slot 15 value (warp-uniform)

    for (int tile = 0; tile < NN / TILE; ++tile) {
        const int n0 = tile * TILE;
        __syncthreads();
        for (int t = tid; t < TILE; t += SCAN_TPB) {
            float x = pcb[n0 + t];
            float y = pcb[NN + n0 + t];
            float z = pcb[2 * NN + n0 + t];
            spts[t] = make_float4(x, y, z, fmaf(x, x, fmaf(y, y, z * z)));
        }
        __syncthreads();

#pragma unroll 4
        for (int i = 0; i < TILE / 32; ++i) {
            float4 p = spts[i * 32 + lane];
            float sc = fmaf(p.x, qx2, fmaf(p.y, qy2, fmaf(p.z, qz2, p.w)));
            unsigned ball = __ballot_sync(0xffffffffu, sc < thr);
            while (ball) {                         // process candidates in index order
                int src = __ffs(ball) - 1;
                ball &= ball - 1;
                float v = __shfl_sync(0xffffffffu, sc, src);
                if (v < thr) {                     // re-check against tightened thr (uniform)
                    int vi = n0 + i * 32 + src;
                    float prev = __shfl_up_sync(0xffffffffu, vs, 1);
                    int  previ = __shfl_up_sync(0xffffffffu, vix, 1);
                    if (lane == 0) prev = -FLTMAX;
                    bool cprev = v < prev;         // insertion below slot l-1 -> shift
                    bool cm    = v < vs;           // insertion at/above this slot
                    vix = cprev ? previ : (cm ? vi : vix);
                    vs  = fminf(fmaxf(v, prev), vs);
                    thr = __shfl_sync(0xffffffffu, vs, 15);
                }
            }
        }
    }

    // ================= fused epilogue (per warp) =================
    // Exact d2 for this lane's neighbor (matches reference weight formula).
    const int n = vix;                 // valid index for all lanes (garbage slots hold real idx)
    const float px = pcb[n], py = pcb[NN + n], pz = pcb[2 * NN + n];
    const float dx = px - qx, dy = py - qy, dz = pz - qz;
    const float d2 = fmaf(dx, dx, fmaf(dy, dy, dz * dz));

    float d2m = (lane < KK) ? d2 : FLTMAX;        // warp-min over the 16 real slots
#pragma unroll
    for (int o = 16; o >= 1; o >>= 1) d2m = fminf(d2m, __shfl_xor_sync(0xffffffffu, d2m, o));

    const float tv = __ldg(temp);
    const float inv_sigma = 1.0f / fmaxf(tv * tv, MIN_SIGMA_C);

    float wgt = (lane < KK) ? __expf((d2m - d2) * inv_sigma) : 0.0f;
    float wsum = wgt;
#pragma unroll
    for (int o = 16; o >= 1; o >>= 1) wsum += __shfl_xor_sync(0xffffffffu, wsum, o);
    wgt *= 1.0f / wsum;

    // projected points: warp reductions of wgt * (px,py,pz)
    float sx = wgt * px, sy = wgt * py, sz = wgt * pz;
#pragma unroll
    for (int o = 16; o >= 1; o >>= 1) {
        sx += __shfl_xor_sync(0xffffffffu, sx, o);
        sy += __shfl_xor_sync(0xffffffffu, sy, o);
        sz += __shfl_xor_sync(0xffffffffu, sz, o);
    }
    if (lane == 0) { spp[w][0] = sx; spp[w][1] = sy; spp[w][2] = sz; }

    // features: per neighbor j broadcast (w_j, n_j); 32 lanes load float2 (coalesced 256B)
    const float* fbase = g_featT + (size_t)b * NN * FF;
    float ax = 0.0f, ay = 0.0f;
#pragma unroll
    for (int j = 0; j < KK; ++j) {
        float wj = __shfl_sync(0xffffffffu, wgt, j);
        int   nj = __shfl_sync(0xffffffffu, vix, j);
        float2 v = *reinterpret_cast<const float2*>(fbase + (size_t)nj * FF + 2 * lane);
        ax = fmaf(wj, v.x, ax);
        ay = fmaf(wj, v.y, ay);
    }
    sfeat[w][2 * lane]     = ax;
    sfeat[w][2 * lane + 1] = ay;
    __syncthreads();

    // ---- coalesced block-wide stores (16 consecutive m per segment) ----
    if (tid < 3 * QW) {                                  // projected (B,3,M)
        int d = tid >> 4, ql = tid & 15;
        out[((size_t)b * 3 + d) * MM + m0 + ql] = spp[ql][d];
    }
    float* outf = out + (size_t)BB * 3 * MM;             // propagated (B,F,M)
#pragma unroll
    for (int r = 0; r < (QW * FF) / SCAN_TPB; ++r) {
        int idx = r * SCAN_TPB + tid;
        int f = idx >> 4, ql = idx & 15;
        outf[((size_t)b * FF + f) * MM + m0 + ql] = sfeat[ql][f];
    }
}

// ================= launch =================
extern "C" void kernel_launch(void* const* d_in, const int* in_sizes, int n_in,
                              void* d_out, int out_size) {
    const float* point_cloud    = (const float*)d_in[0];  // (B, 3, N)
    const float* query_cloud    = (const float*)d_in[1];  // (B, 3, M)
    const float* point_features = (const float*)d_in[2];  // (B, F, N)
    const float* temperature    = (const float*)d_in[3];  // scalar
    float* out = (float*)d_out;  // [projected (B,3,M) | propagated (B,F,M)]

    (void)in_sizes; (void)n_in; (void)out_size;

    dim3 tgrid(NN / 32, FF / 32, BB);
    dim3 tblk(32, 8);
    transpose_kernel<<<tgrid, tblk>>>(point_features);

    dim3 sgrid(MM / QW, BB);
    fused_kernel<<<sgrid, SCAN_TPB>>>(point_cloud, query_cloud, temperature, (float*)d_out);
}